// round 3
// baseline (speedup 1.0000x reference)
#include <cuda_runtime.h>

#define NBLK 128
#define NTHR 512
#define BB   128
#define TT   512
#define PREDN 24
#define FF   16
#define LL   8
#define HH   1024
#define FROWS (TT + PREDN - 1)
#define KT   32

typedef unsigned long long ull;

// Persistent device scratch
__device__ float g_h0[2][BB * HH];
__device__ float g_h1[2][BB * HH];
__device__ float g_p[BB * LL];
__device__ unsigned g_count = 0;
__device__ unsigned g_gen = 0;

// ---------------- grid-wide sense-reversing barrier -------------------------
__device__ __forceinline__ void gbar() {
    __syncthreads();
    if (threadIdx.x == 0) {
        __threadfence();
        volatile unsigned* vg = &g_gen;
        unsigned g = *vg;
        if (atomicAdd(&g_count, 1u) == NBLK - 1) {
            g_count = 0;
            __threadfence();
            *vg = g + 1;
        } else {
            while (*vg == g) {}
        }
        __threadfence();
    }
    __syncthreads();
}

// group barrier: 256 threads, named barrier kh+1
__device__ __forceinline__ void barg(int kh) {
    asm volatile("bar.sync %0, 256;" :: "r"(kh + 1) : "memory");
}

// ---------------- GEMM slice with f32x2 packed FMA --------------------------
// Group of 256 threads computes C[128 b][24 cols] over k range
// [kbase, kbase + ntiles*KT). Thread (tu,tb) accumulates 4 consecutive b rows
// (pairs b01/b23 packed in f32x2) x 3 gate columns.
__device__ __forceinline__ void gemm_part(
    const float* __restrict__ hsrc, const float* __restrict__ W,
    int kbase, int ntiles, int u0, int tu, int tb, int kh, int t,
    ull a01[3], ull a23[3],
    float* __restrict__ shh,   // [KT][128]
    float* __restrict__ shw)   // [KT][24][2]  (weights duplicated)
{
    const int s = t & 255;
    // h staging role: b = s&127, k half = (s>>7)*16
    const int hb = s & 127;
    const int hhalf = (s >> 7) << 4;
    const float* hrow = hsrc + (long)hb * HH + kbase + hhalf;
    // w staging role: first 192 threads
    const bool wact = (s < 192);
    const int wcol = s >> 3;            // 0..23
    const int wk4 = (s & 7) << 2;       // 0..28
    const float* wrow = W;
    if (wact)
        wrow = W + (long)((wcol >> 3) * HH + u0 + (wcol & 7)) * HH + kbase + wk4;

    float4 h0v, h1v, h2v, h3v, wv;
    {   // prefetch tile 0
        const float4* hp = reinterpret_cast<const float4*>(hrow);
        h0v = __ldcg(hp); h1v = __ldcg(hp + 1); h2v = __ldcg(hp + 2); h3v = __ldcg(hp + 3);
        if (wact) wv = __ldg(reinterpret_cast<const float4*>(wrow));
    }

    const float* hcomp = shh + 4 * tb;
    const float* wcomp = shw + 2 * tu;

    for (int tile = 0; tile < ntiles; tile++) {
        barg(kh);   // buffer free (prev compute done in this group)
        // transposed h stage: shh[k][b]
        shh[(hhalf + 0) * 128 + hb] = h0v.x; shh[(hhalf + 1) * 128 + hb] = h0v.y;
        shh[(hhalf + 2) * 128 + hb] = h0v.z; shh[(hhalf + 3) * 128 + hb] = h0v.w;
        shh[(hhalf + 4) * 128 + hb] = h1v.x; shh[(hhalf + 5) * 128 + hb] = h1v.y;
        shh[(hhalf + 6) * 128 + hb] = h1v.z; shh[(hhalf + 7) * 128 + hb] = h1v.w;
        shh[(hhalf + 8) * 128 + hb] = h2v.x; shh[(hhalf + 9) * 128 + hb] = h2v.y;
        shh[(hhalf + 10) * 128 + hb] = h2v.z; shh[(hhalf + 11) * 128 + hb] = h2v.w;
        shh[(hhalf + 12) * 128 + hb] = h3v.x; shh[(hhalf + 13) * 128 + hb] = h3v.y;
        shh[(hhalf + 14) * 128 + hb] = h3v.z; shh[(hhalf + 15) * 128 + hb] = h3v.w;
        if (wact) {
            float2* wp = reinterpret_cast<float2*>(shw);
            wp[(wk4 + 0) * 24 + wcol] = make_float2(wv.x, wv.x);
            wp[(wk4 + 1) * 24 + wcol] = make_float2(wv.y, wv.y);
            wp[(wk4 + 2) * 24 + wcol] = make_float2(wv.z, wv.z);
            wp[(wk4 + 3) * 24 + wcol] = make_float2(wv.w, wv.w);
        }
        barg(kh);   // staged data visible

        if (tile + 1 < ntiles) {   // prefetch next tile into regs
            const float4* hp = reinterpret_cast<const float4*>(hrow + (tile + 1) * KT);
            h0v = __ldcg(hp); h1v = __ldcg(hp + 1); h2v = __ldcg(hp + 2); h3v = __ldcg(hp + 3);
            if (wact) wv = __ldg(reinterpret_cast<const float4*>(wrow + (tile + 1) * KT));
        }

        #pragma unroll
        for (int kk = 0; kk < KT; kk++) {
            ulonglong2 hp2 = *reinterpret_cast<const ulonglong2*>(hcomp + kk * 128);
            #pragma unroll
            for (int g = 0; g < 3; g++) {
                ull wpair = *reinterpret_cast<const ull*>(wcomp + kk * 48 + g * 16);
                asm("fma.rn.f32x2 %0, %1, %2, %0;" : "+l"(a01[g]) : "l"(hp2.x), "l"(wpair));
                asm("fma.rn.f32x2 %0, %1, %2, %0;" : "+l"(a23[g]) : "l"(hp2.y), "l"(wpair));
            }
        }
    }
}

// ---------------- partial exchange: kh1 -> kh0 ------------------------------
__device__ __forceinline__ void xfer(int t, int kh,
                                     const ull a01[3], const ull a23[3],
                                     float oth[3][4], float* __restrict__ red) {
    __syncthreads();
    if (kh == 1) {
        float2* rp = reinterpret_cast<float2*>(red) + (t & 255) * 6;
        rp[0] = *reinterpret_cast<const float2*>(&a01[0]);
        rp[1] = *reinterpret_cast<const float2*>(&a23[0]);
        rp[2] = *reinterpret_cast<const float2*>(&a01[1]);
        rp[3] = *reinterpret_cast<const float2*>(&a23[1]);
        rp[4] = *reinterpret_cast<const float2*>(&a01[2]);
        rp[5] = *reinterpret_cast<const float2*>(&a23[2]);
    }
    __syncthreads();
    if (kh == 0) {
        const float2* rp = reinterpret_cast<const float2*>(red) + t * 6;
        #pragma unroll
        for (int g = 0; g < 3; g++) {
            float2 p = rp[2 * g], q = rp[2 * g + 1];
            oth[g][0] = p.x; oth[g][1] = p.y; oth[g][2] = q.x; oth[g][3] = q.y;
        }
    }
}

__device__ __forceinline__ void unpack(const ull a01[3], const ull a23[3], float o[3][4]) {
    #pragma unroll
    for (int g = 0; g < 3; g++) {
        float2 p = *reinterpret_cast<const float2*>(&a01[g]);
        float2 q = *reinterpret_cast<const float2*>(&a23[g]);
        o[g][0] = p.x; o[g][1] = p.y; o[g][2] = q.x; o[g][3] = q.y;
    }
}

// ---------------- small input projection (K = 24) ---------------------------
__device__ __forceinline__ void load_wi_slice(const float* __restrict__ Wih, int u0,
                                              float* __restrict__ sh_wi) {
    for (int idx = threadIdx.x; idx < 24 * 24; idx += NTHR) {
        int jl = idx / 24, k = idx % 24;
        int g = jl >> 3, uu = jl & 7;
        sh_wi[k * 24 + jl] = Wih[(long)(g * HH + u0 + uu) * 24 + k];
    }
}

__device__ __forceinline__ void input_acc24(const float* __restrict__ sh_x,
                                            const float* __restrict__ sh_wi,
                                            int tu, int b0, float ai[3][4]) {
    #pragma unroll
    for (int g = 0; g < 3; g++)
        #pragma unroll
        for (int i = 0; i < 4; i++) ai[g][i] = 0.f;
    #pragma unroll
    for (int k = 0; k < 24; k++) {
        float w0 = sh_wi[k * 24 + tu];
        float w1 = sh_wi[k * 24 + 8 + tu];
        float w2 = sh_wi[k * 24 + 16 + tu];
        #pragma unroll
        for (int i = 0; i < 4; i++) {
            float xv = sh_x[(b0 + i) * 25 + k];
            ai[0][i] += xv * w0; ai[1][i] += xv * w1; ai[2][i] += xv * w2;
        }
    }
}

// ---------------- GRU pointwise update --------------------------------------
__device__ __forceinline__ void gru_update(const float ai[3][4], const float ah[3][4],
                                           const float* __restrict__ bih,
                                           const float* __restrict__ bhh,
                                           int jcol, int b0,
                                           const float* __restrict__ hcur,
                                           float* __restrict__ hnxt) {
    float bir = bih[jcol], biz = bih[HH + jcol], bin = bih[2 * HH + jcol];
    float bhr = bhh[jcol], bhz = bhh[HH + jcol], bhn = bhh[2 * HH + jcol];
    #pragma unroll
    for (int i = 0; i < 4; i++) {
        int b = b0 + i;
        float r = 1.f / (1.f + __expf(-(ai[0][i] + bir + ah[0][i] + bhr)));
        float z = 1.f / (1.f + __expf(-(ai[1][i] + biz + ah[1][i] + bhz)));
        float n = tanhf(ai[2][i] + bin + r * (ah[2][i] + bhn));
        float ho = __ldcg(hcur + (long)b * HH + jcol);
        __stcg(hnxt + (long)b * HH + jcol, (1.f - z) * n + z * ho);
    }
}

// ---------------- FC head ----------------------------------------------------
__device__ __forceinline__ void fc_phase(const float* __restrict__ h,
                                         const float* __restrict__ fcW,
                                         const float* __restrict__ fcb,
                                         float* __restrict__ outp) {
    int b = blockIdx.x;
    int w = threadIdx.x >> 5;
    int lane = threadIdx.x & 31;
    float s = 0.f;
    #pragma unroll
    for (int c = 0; c < 32; c++)
        s += __ldcg(h + (long)b * HH + 32 * c + lane) * fcW[(long)w * HH + 32 * c + lane];
    #pragma unroll
    for (int o = 16; o; o >>= 1) s += __shfl_down_sync(0xffffffffu, s, o);
    if (lane == 0) {
        float v = s + fcb[w];
        outp[b * LL + w] = v;
        __stcg(g_p + b * LL + w, v);
    }
}

// ---------------- persistent kernel -----------------------------------------
__global__ void __launch_bounds__(NTHR, 1) gru_persistent(
    const float* __restrict__ feats, const float* __restrict__ labels,
    const float* __restrict__ y, const int* __restrict__ teacher,
    const float* __restrict__ eWih0, const float* __restrict__ eWhh0,
    const float* __restrict__ ebih0, const float* __restrict__ ebhh0,
    const float* __restrict__ eWih1, const float* __restrict__ eWhh1,
    const float* __restrict__ ebih1, const float* __restrict__ ebhh1,
    const float* __restrict__ dWih, const float* __restrict__ dWhh,
    const float* __restrict__ dbih, const float* __restrict__ dbhh,
    const float* __restrict__ fcW, const float* __restrict__ fcb,
    float* __restrict__ out)
{
    // shared pool (46.25 KB), manually unioned:
    //   [0    .. 8192)  sh_h[2][KT][128]   (sh_x 3200 floats overlaps group0 tile)
    //   [8192 .. 11264) sh_w[2][KT*48]     (red 3072 floats overlaps)
    //   [11264.. 11840) sh_wi 576 floats
    __shared__ __align__(16) float smem[11840];
    float* sh_h  = smem;
    float* sh_w  = smem + 8192;
    float* sh_x  = smem;
    float* red   = smem + 8192;
    float* sh_wi = smem + 11264;

    const int t  = threadIdx.x;
    const int tu = t & 7;
    const int tb = (t >> 3) & 31;
    const int kh = t >> 8;
    const int b0 = tb * 4;
    const int u0 = blockIdx.x * 8;
    const int jcol = u0 + tu;
    const int teach = teacher[0];
    float* shh = sh_h + kh * (KT * 128);
    float* shw = sh_w + kh * (KT * 48);

    for (int i = blockIdx.x * NTHR + t; i < BB * HH; i += NBLK * NTHR) {
        g_h0[0][i] = 0.f;
        g_h1[0][i] = 0.f;
    }
    load_wi_slice(eWih0, u0, sh_wi);
    gbar();

    int cur = 0;
    // ================= encoder ==============================================
    for (int step = 0; step < TT; step++) {
        for (int idx = t; idx < BB * 24; idx += NTHR) {
            int b = idx / 24, k = idx % 24;
            float v = (k < FF) ? feats[((long)b * FROWS + step) * FF + k]
                               : labels[((long)b * TT + step) * LL + (k - FF)];
            sh_x[b * 25 + k] = v;
        }
        __syncthreads();

        // layer 0: split-K recurrent GEMM (+ tiny input projection on kh0)
        float ai[3][4];
        if (kh == 0) input_acc24(sh_x, sh_wi, tu, b0, ai);
        ull a01[3] = {0, 0, 0}, a23[3] = {0, 0, 0};
        gemm_part(g_h0[cur], eWhh0, kh * 512, 16, u0, tu, tb, kh, t, a01, a23, shh, shw);
        float oth[3][4];
        xfer(t, kh, a01, a23, oth, red);
        if (kh == 0) {
            float own[3][4], ah[3][4];
            unpack(a01, a23, own);
            #pragma unroll
            for (int g = 0; g < 3; g++)
                #pragma unroll
                for (int i = 0; i < 4; i++) ah[g][i] = own[g][i] + oth[g][i];
            gru_update(ai, ah, ebih0, ebhh0, jcol, b0, g_h0[cur], g_h0[cur ^ 1]);
        }
        gbar();

        // layer 1: dual GEMM (kh0 = Wih1 @ h0_next, kh1 = Whh1 @ h1_cur)
        a01[0] = a01[1] = a01[2] = 0; a23[0] = a23[1] = a23[2] = 0;
        gemm_part(kh ? g_h1[cur] : g_h0[cur ^ 1], kh ? eWhh1 : eWih1,
                  0, 32, u0, tu, tb, kh, t, a01, a23, shh, shw);
        xfer(t, kh, a01, a23, oth, red);
        if (kh == 0) {
            float gi[3][4];
            unpack(a01, a23, gi);
            gru_update(gi, oth, ebih1, ebhh1, jcol, b0, g_h1[cur], g_h1[cur ^ 1]);
        }
        gbar();
        cur ^= 1;
    }

    if (t < 256) fc_phase(g_h1[cur], fcW, fcb, out);
    load_wi_slice(dWih, u0, sh_wi);
    gbar();

    // ================= decoder ==============================================
    for (int s = 0; s < PREDN - 1; s++) {
        for (int idx = t; idx < BB * 24; idx += NTHR) {
            int b = idx / 24, k = idx % 24;
            float v;
            if (k < FF)      v = feats[((long)b * FROWS + TT + s) * FF + k];
            else if (teach)  v = y[((long)b * (PREDN - 1) + s) * LL + (k - FF)];
            else             v = __ldcg(g_p + b * LL + (k - FF));
            sh_x[b * 25 + k] = v;
        }
        __syncthreads();

        float ai[3][4];
        if (kh == 0) input_acc24(sh_x, sh_wi, tu, b0, ai);
        ull a01[3] = {0, 0, 0}, a23[3] = {0, 0, 0};
        gemm_part(g_h1[cur], dWhh, kh * 512, 16, u0, tu, tb, kh, t, a01, a23, shh, shw);
        float oth[3][4];
        xfer(t, kh, a01, a23, oth, red);
        if (kh == 0) {
            float own[3][4], ah[3][4];
            unpack(a01, a23, own);
            #pragma unroll
            for (int g = 0; g < 3; g++)
                #pragma unroll
                for (int i = 0; i < 4; i++) ah[g][i] = own[g][i] + oth[g][i];
            gru_update(ai, ah, dbih, dbhh, jcol, b0, g_h1[cur], g_h1[cur ^ 1]);
        }
        gbar();

        if (t < 256) fc_phase(g_h1[cur ^ 1], fcW, fcb, out + (long)(s + 1) * BB * LL);
        gbar();
        cur ^= 1;
    }
}

extern "C" void kernel_launch(void* const* d_in, const int* in_sizes, int n_in,
                              void* d_out, int out_size) {
    const float* feats  = (const float*)d_in[0];
    const float* labels = (const float*)d_in[1];
    const float* y      = (const float*)d_in[2];
    const int*   teach  = (const int*)d_in[3];
    const float* eWih0  = (const float*)d_in[4];
    const float* eWhh0  = (const float*)d_in[5];
    const float* ebih0  = (const float*)d_in[6];
    const float* ebhh0  = (const float*)d_in[7];
    const float* eWih1  = (const float*)d_in[8];
    const float* eWhh1  = (const float*)d_in[9];
    const float* ebih1  = (const float*)d_in[10];
    const float* ebhh1  = (const float*)d_in[11];
    const float* dWih   = (const float*)d_in[12];
    const float* dWhh   = (const float*)d_in[13];
    const float* dbih   = (const float*)d_in[14];
    const float* dbhh   = (const float*)d_in[15];
    const float* fcW    = (const float*)d_in[16];
    const float* fcb    = (const float*)d_in[17];
    float* out = (float*)d_out;

    gru_persistent<<<NBLK, NTHR>>>(feats, labels, y, teach,
                                   eWih0, eWhh0, ebih0, ebhh0,
                                   eWih1, eWhh1, ebih1, ebhh1,
                                   dWih, dWhh, dbih, dbhh,
                                   fcW, fcb, out);
}

// round 4
// speedup vs baseline: 1.0017x; 1.0017x over previous
#include <cuda_runtime.h>

#define NBLK 128
#define NTHR 512
#define BB   128
#define TT   512
#define PREDN 24
#define FF   16
#define LL   8
#define HH   1024
#define FROWS (TT + PREDN - 1)
#define KT   32

typedef unsigned long long ull;

// Persistent device scratch
__device__ float g_h0[2][BB * HH];
__device__ float g_h1[2][BB * HH];
__device__ float g_p[BB * LL];
__device__ unsigned g_count = 0;
__device__ unsigned g_gen = 0;

// ---------------- grid-wide sense-reversing barrier -------------------------
__device__ __forceinline__ void gbar() {
    __syncthreads();
    if (threadIdx.x == 0) {
        __threadfence();
        volatile unsigned* vg = &g_gen;
        unsigned g = *vg;
        if (atomicAdd(&g_count, 1u) == NBLK - 1) {
            g_count = 0;
            __threadfence();
            *vg = g + 1;
        } else {
            while (*vg == g) {}
        }
        __threadfence();
    }
    __syncthreads();
}

// group barrier: 256 threads, named barrier kh+1
__device__ __forceinline__ void barg(int kh) {
    asm volatile("bar.sync %0, 256;" :: "r"(kh + 1) : "memory");
}

// ---------------- GEMM slice with f32x2 packed FMA --------------------------
// Group of 256 threads computes C[128 b][24 cols] over k range
// [kbase, kbase + ntiles*KT). Thread (tu,tb) accumulates 4 consecutive b rows
// (pairs b01/b23 packed in f32x2) x 3 gate columns.
__device__ __forceinline__ void gemm_part(
    const float* __restrict__ hsrc, const float* __restrict__ W,
    int kbase, int ntiles, int u0, int tu, int tb, int kh, int t,
    ull a01[3], ull a23[3],
    float* __restrict__ shh,   // [KT][128]
    float* __restrict__ shw)   // [KT][24][2]  (weights duplicated)
{
    const int s = t & 255;
    // h staging role: b = s&127, k half = (s>>7)*16
    const int hb = s & 127;
    const int hhalf = (s >> 7) << 4;
    const float* hrow = hsrc + (long)hb * HH + kbase + hhalf;
    // w staging role: first 192 threads
    const bool wact = (s < 192);
    const int wcol = s >> 3;            // 0..23
    const int wk4 = (s & 7) << 2;       // 0..28
    const float* wrow = W;
    if (wact)
        wrow = W + (long)((wcol >> 3) * HH + u0 + (wcol & 7)) * HH + kbase + wk4;

    float4 h0v, h1v, h2v, h3v, wv;
    {   // prefetch tile 0
        const float4* hp = reinterpret_cast<const float4*>(hrow);
        h0v = __ldcg(hp); h1v = __ldcg(hp + 1); h2v = __ldcg(hp + 2); h3v = __ldcg(hp + 3);
        if (wact) wv = __ldg(reinterpret_cast<const float4*>(wrow));
    }

    const float* hcomp = shh + 4 * tb;
    const float* wcomp = shw + 2 * tu;

    for (int tile = 0; tile < ntiles; tile++) {
        barg(kh);   // buffer free (prev compute done in this group)
        // transposed h stage: shh[k][b]
        shh[(hhalf + 0) * 128 + hb] = h0v.x; shh[(hhalf + 1) * 128 + hb] = h0v.y;
        shh[(hhalf + 2) * 128 + hb] = h0v.z; shh[(hhalf + 3) * 128 + hb] = h0v.w;
        shh[(hhalf + 4) * 128 + hb] = h1v.x; shh[(hhalf + 5) * 128 + hb] = h1v.y;
        shh[(hhalf + 6) * 128 + hb] = h1v.z; shh[(hhalf + 7) * 128 + hb] = h1v.w;
        shh[(hhalf + 8) * 128 + hb] = h2v.x; shh[(hhalf + 9) * 128 + hb] = h2v.y;
        shh[(hhalf + 10) * 128 + hb] = h2v.z; shh[(hhalf + 11) * 128 + hb] = h2v.w;
        shh[(hhalf + 12) * 128 + hb] = h3v.x; shh[(hhalf + 13) * 128 + hb] = h3v.y;
        shh[(hhalf + 14) * 128 + hb] = h3v.z; shh[(hhalf + 15) * 128 + hb] = h3v.w;
        if (wact) {
            float2* wp = reinterpret_cast<float2*>(shw);
            wp[(wk4 + 0) * 24 + wcol] = make_float2(wv.x, wv.x);
            wp[(wk4 + 1) * 24 + wcol] = make_float2(wv.y, wv.y);
            wp[(wk4 + 2) * 24 + wcol] = make_float2(wv.z, wv.z);
            wp[(wk4 + 3) * 24 + wcol] = make_float2(wv.w, wv.w);
        }
        barg(kh);   // staged data visible

        if (tile + 1 < ntiles) {   // prefetch next tile into regs
            const float4* hp = reinterpret_cast<const float4*>(hrow + (tile + 1) * KT);
            h0v = __ldcg(hp); h1v = __ldcg(hp + 1); h2v = __ldcg(hp + 2); h3v = __ldcg(hp + 3);
            if (wact) wv = __ldg(reinterpret_cast<const float4*>(wrow + (tile + 1) * KT));
        }

        #pragma unroll
        for (int kk = 0; kk < KT; kk++) {
            ulonglong2 hp2 = *reinterpret_cast<const ulonglong2*>(hcomp + kk * 128);
            #pragma unroll
            for (int g = 0; g < 3; g++) {
                ull wpair = *reinterpret_cast<const ull*>(wcomp + kk * 48 + g * 16);
                asm("fma.rn.f32x2 %0, %1, %2, %0;" : "+l"(a01[g]) : "l"(hp2.x), "l"(wpair));
                asm("fma.rn.f32x2 %0, %1, %2, %0;" : "+l"(a23[g]) : "l"(hp2.y), "l"(wpair));
            }
        }
    }
}

// ---------------- partial exchange: kh1 -> kh0 ------------------------------
__device__ __forceinline__ void xfer(int t, int kh,
                                     const ull a01[3], const ull a23[3],
                                     float oth[3][4], float* __restrict__ red) {
    __syncthreads();
    if (kh == 1) {
        float2* rp = reinterpret_cast<float2*>(red) + (t & 255) * 6;
        rp[0] = *reinterpret_cast<const float2*>(&a01[0]);
        rp[1] = *reinterpret_cast<const float2*>(&a23[0]);
        rp[2] = *reinterpret_cast<const float2*>(&a01[1]);
        rp[3] = *reinterpret_cast<const float2*>(&a23[1]);
        rp[4] = *reinterpret_cast<const float2*>(&a01[2]);
        rp[5] = *reinterpret_cast<const float2*>(&a23[2]);
    }
    __syncthreads();
    if (kh == 0) {
        const float2* rp = reinterpret_cast<const float2*>(red) + t * 6;
        #pragma unroll
        for (int g = 0; g < 3; g++) {
            float2 p = rp[2 * g], q = rp[2 * g + 1];
            oth[g][0] = p.x; oth[g][1] = p.y; oth[g][2] = q.x; oth[g][3] = q.y;
        }
    }
}

__device__ __forceinline__ void unpack(const ull a01[3], const ull a23[3], float o[3][4]) {
    #pragma unroll
    for (int g = 0; g < 3; g++) {
        float2 p = *reinterpret_cast<const float2*>(&a01[g]);
        float2 q = *reinterpret_cast<const float2*>(&a23[g]);
        o[g][0] = p.x; o[g][1] = p.y; o[g][2] = q.x; o[g][3] = q.y;
    }
}

// ---------------- small input projection (K = 24) ---------------------------
__device__ __forceinline__ void load_wi_slice(const float* __restrict__ Wih, int u0,
                                              float* __restrict__ sh_wi) {
    for (int idx = threadIdx.x; idx < 24 * 24; idx += NTHR) {
        int jl = idx / 24, k = idx % 24;
        int g = jl >> 3, uu = jl & 7;
        sh_wi[k * 24 + jl] = Wih[(long)(g * HH + u0 + uu) * 24 + k];
    }
}

__device__ __forceinline__ void input_acc24(const float* __restrict__ sh_x,
                                            const float* __restrict__ sh_wi,
                                            int tu, int b0, float ai[3][4]) {
    #pragma unroll
    for (int g = 0; g < 3; g++)
        #pragma unroll
        for (int i = 0; i < 4; i++) ai[g][i] = 0.f;
    #pragma unroll
    for (int k = 0; k < 24; k++) {
        float w0 = sh_wi[k * 24 + tu];
        float w1 = sh_wi[k * 24 + 8 + tu];
        float w2 = sh_wi[k * 24 + 16 + tu];
        #pragma unroll
        for (int i = 0; i < 4; i++) {
            float xv = sh_x[(b0 + i) * 25 + k];
            ai[0][i] += xv * w0; ai[1][i] += xv * w1; ai[2][i] += xv * w2;
        }
    }
}

// ---------------- GRU pointwise update --------------------------------------
__device__ __forceinline__ void gru_update(const float ai[3][4], const float ah[3][4],
                                           const float* __restrict__ bih,
                                           const float* __restrict__ bhh,
                                           int jcol, int b0,
                                           const float* __restrict__ hcur,
                                           float* __restrict__ hnxt) {
    float bir = bih[jcol], biz = bih[HH + jcol], bin = bih[2 * HH + jcol];
    float bhr = bhh[jcol], bhz = bhh[HH + jcol], bhn = bhh[2 * HH + jcol];
    #pragma unroll
    for (int i = 0; i < 4; i++) {
        int b = b0 + i;
        float r = 1.f / (1.f + __expf(-(ai[0][i] + bir + ah[0][i] + bhr)));
        float z = 1.f / (1.f + __expf(-(ai[1][i] + biz + ah[1][i] + bhz)));
        float n = tanhf(ai[2][i] + bin + r * (ah[2][i] + bhn));
        float ho = __ldcg(hcur + (long)b * HH + jcol);
        __stcg(hnxt + (long)b * HH + jcol, (1.f - z) * n + z * ho);
    }
}

// ---------------- FC head ----------------------------------------------------
__device__ __forceinline__ void fc_phase(const float* __restrict__ h,
                                         const float* __restrict__ fcW,
                                         const float* __restrict__ fcb,
                                         float* __restrict__ outp) {
    int b = blockIdx.x;
    int w = threadIdx.x >> 5;
    int lane = threadIdx.x & 31;
    float s = 0.f;
    #pragma unroll
    for (int c = 0; c < 32; c++)
        s += __ldcg(h + (long)b * HH + 32 * c + lane) * fcW[(long)w * HH + 32 * c + lane];
    #pragma unroll
    for (int o = 16; o; o >>= 1) s += __shfl_down_sync(0xffffffffu, s, o);
    if (lane == 0) {
        float v = s + fcb[w];
        outp[b * LL + w] = v;
        __stcg(g_p + b * LL + w, v);
    }
}

// ---------------- persistent kernel -----------------------------------------
__global__ void __launch_bounds__(NTHR, 1) gru_persistent(
    const float* __restrict__ feats, const float* __restrict__ labels,
    const float* __restrict__ y, const int* __restrict__ teacher,
    const float* __restrict__ eWih0, const float* __restrict__ eWhh0,
    const float* __restrict__ ebih0, const float* __restrict__ ebhh0,
    const float* __restrict__ eWih1, const float* __restrict__ eWhh1,
    const float* __restrict__ ebih1, const float* __restrict__ ebhh1,
    const float* __restrict__ dWih, const float* __restrict__ dWhh,
    const float* __restrict__ dbih, const float* __restrict__ dbhh,
    const float* __restrict__ fcW, const float* __restrict__ fcb,
    float* __restrict__ out)
{
    // shared pool (46.25 KB), manually unioned:
    //   [0    .. 8192)  sh_h[2][KT][128]   (sh_x 3200 floats overlaps group0 tile)
    //   [8192 .. 11264) sh_w[2][KT*48]     (red 3072 floats overlaps)
    //   [11264.. 11840) sh_wi 576 floats
    __shared__ __align__(16) float smem[11840];
    float* sh_h  = smem;
    float* sh_w  = smem + 8192;
    float* sh_x  = smem;
    float* red   = smem + 8192;
    float* sh_wi = smem + 11264;

    const int t  = threadIdx.x;
    const int tu = t & 7;
    const int tb = (t >> 3) & 31;
    const int kh = t >> 8;
    const int b0 = tb * 4;
    const int u0 = blockIdx.x * 8;
    const int jcol = u0 + tu;
    const int teach = teacher[0];
    float* shh = sh_h + kh * (KT * 128);
    float* shw = sh_w + kh * (KT * 48);

    for (int i = blockIdx.x * NTHR + t; i < BB * HH; i += NBLK * NTHR) {
        g_h0[0][i] = 0.f;
        g_h1[0][i] = 0.f;
    }
    load_wi_slice(eWih0, u0, sh_wi);
    gbar();

    int cur = 0;
    // ================= encoder ==============================================
    for (int step = 0; step < TT; step++) {
        for (int idx = t; idx < BB * 24; idx += NTHR) {
            int b = idx / 24, k = idx % 24;
            float v = (k < FF) ? feats[((long)b * FROWS + step) * FF + k]
                               : labels[((long)b * TT + step) * LL + (k - FF)];
            sh_x[b * 25 + k] = v;
        }
        __syncthreads();

        // layer 0: split-K recurrent GEMM (+ tiny input projection on kh0)
        float ai[3][4];
        if (kh == 0) input_acc24(sh_x, sh_wi, tu, b0, ai);
        ull a01[3] = {0, 0, 0}, a23[3] = {0, 0, 0};
        gemm_part(g_h0[cur], eWhh0, kh * 512, 16, u0, tu, tb, kh, t, a01, a23, shh, shw);
        float oth[3][4];
        xfer(t, kh, a01, a23, oth, red);
        if (kh == 0) {
            float own[3][4], ah[3][4];
            unpack(a01, a23, own);
            #pragma unroll
            for (int g = 0; g < 3; g++)
                #pragma unroll
                for (int i = 0; i < 4; i++) ah[g][i] = own[g][i] + oth[g][i];
            gru_update(ai, ah, ebih0, ebhh0, jcol, b0, g_h0[cur], g_h0[cur ^ 1]);
        }
        gbar();

        // layer 1: dual GEMM (kh0 = Wih1 @ h0_next, kh1 = Whh1 @ h1_cur)
        a01[0] = a01[1] = a01[2] = 0; a23[0] = a23[1] = a23[2] = 0;
        gemm_part(kh ? g_h1[cur] : g_h0[cur ^ 1], kh ? eWhh1 : eWih1,
                  0, 32, u0, tu, tb, kh, t, a01, a23, shh, shw);
        xfer(t, kh, a01, a23, oth, red);
        if (kh == 0) {
            float gi[3][4];
            unpack(a01, a23, gi);
            gru_update(gi, oth, ebih1, ebhh1, jcol, b0, g_h1[cur], g_h1[cur ^ 1]);
        }
        gbar();
        cur ^= 1;
    }

    if (t < 256) fc_phase(g_h1[cur], fcW, fcb, out);
    load_wi_slice(dWih, u0, sh_wi);
    gbar();

    // ================= decoder ==============================================
    for (int s = 0; s < PREDN - 1; s++) {
        for (int idx = t; idx < BB * 24; idx += NTHR) {
            int b = idx / 24, k = idx % 24;
            float v;
            if (k < FF)      v = feats[((long)b * FROWS + TT + s) * FF + k];
            else if (teach)  v = y[((long)b * (PREDN - 1) + s) * LL + (k - FF)];
            else             v = __ldcg(g_p + b * LL + (k - FF));
            sh_x[b * 25 + k] = v;
        }
        __syncthreads();

        float ai[3][4];
        if (kh == 0) input_acc24(sh_x, sh_wi, tu, b0, ai);
        ull a01[3] = {0, 0, 0}, a23[3] = {0, 0, 0};
        gemm_part(g_h1[cur], dWhh, kh * 512, 16, u0, tu, tb, kh, t, a01, a23, shh, shw);
        float oth[3][4];
        xfer(t, kh, a01, a23, oth, red);
        if (kh == 0) {
            float own[3][4], ah[3][4];
            unpack(a01, a23, own);
            #pragma unroll
            for (int g = 0; g < 3; g++)
                #pragma unroll
                for (int i = 0; i < 4; i++) ah[g][i] = own[g][i] + oth[g][i];
            gru_update(ai, ah, dbih, dbhh, jcol, b0, g_h1[cur], g_h1[cur ^ 1]);
        }
        gbar();

        if (t < 256) fc_phase(g_h1[cur ^ 1], fcW, fcb, out + (long)(s + 1) * BB * LL);
        gbar();
        cur ^= 1;
    }
}

extern "C" void kernel_launch(void* const* d_in, const int* in_sizes, int n_in,
                              void* d_out, int out_size) {
    const float* feats  = (const float*)d_in[0];
    const float* labels = (const float*)d_in[1];
    const float* y      = (const float*)d_in[2];
    const int*   teach  = (const int*)d_in[3];
    const float* eWih0  = (const float*)d_in[4];
    const float* eWhh0  = (const float*)d_in[5];
    const float* ebih0  = (const float*)d_in[6];
    const float* ebhh0  = (const float*)d_in[7];
    const float* eWih1  = (const float*)d_in[8];
    const float* eWhh1  = (const float*)d_in[9];
    const float* ebih1  = (const float*)d_in[10];
    const float* ebhh1  = (const float*)d_in[11];
    const float* dWih   = (const float*)d_in[12];
    const float* dWhh   = (const float*)d_in[13];
    const float* dbih   = (const float*)d_in[14];
    const float* dbhh   = (const float*)d_in[15];
    const float* fcW    = (const float*)d_in[16];
    const float* fcb    = (const float*)d_in[17];
    float* out = (float*)d_out;

    gru_persistent<<<NBLK, NTHR>>>(feats, labels, y, teach,
                                   eWih0, eWhh0, ebih0, ebhh0,
                                   eWih1, eWhh1, ebih1, ebhh1,
                                   dWih, dWhh, dbih, dbhh,
                                   fcW, fcb, out);
}